// round 10
// baseline (speedup 1.0000x reference)
#include <cuda_runtime.h>

#define TT 512
typedef unsigned long long ull;
#define EPC 28              // elems per CTA

// ---------- packed f32x2 helpers ----------
__device__ __forceinline__ ull pk2(float a, float b) {
    ull r; asm("mov.b64 %0, {%1,%2};" : "=l"(r) : "f"(a), "f"(b)); return r;
}
__device__ __forceinline__ float sum2(ull v) {
    float a, b; asm("mov.b64 {%0,%1}, %2;" : "=f"(a), "=f"(b) : "l"(v));
    return a + b;
}
__device__ __forceinline__ ull fma2(ull a, ull b, ull c) {
    ull d; asm("fma.rn.f32x2 %0, %1, %2, %3;" : "=l"(d) : "l"(a), "l"(b), "l"(c));
    return d;
}

// ---------- activations ----------
__device__ __forceinline__ float tanhap_(float x) {     // MUFU tanh (recurrence)
    float r; asm("tanh.approx.f32 %0, %1;" : "=f"(r) : "f"(x)); return r;
}
__device__ __forceinline__ float rcpf_(float x) {
    float r; asm("rcp.approx.f32 %0, %1;" : "=f"(r) : "f"(x)); return r;
}
__device__ __forceinline__ float ex2f_(float x) {
    float r; asm("ex2.approx.f32 %0, %1;" : "=f"(r) : "f"(x)); return r;
}
__device__ __forceinline__ float tanh_(float x) {       // accurate (epilogue)
    float e = ex2f_(2.8853900817779268f * x);
    return 1.0f - 2.0f * rcpf_(e + 1.0f);
}

// pairwise named barrier: A-warp wp <-> B-warp wp, 64 threads
#define PBAR(id) asm volatile("bar.sync %0, %1;" :: "r"(id), "r"(64) : "memory")

// load 16 floats (64B, 16B-aligned smem row) as 8 packed f32x2
__device__ __forceinline__ void ld8u(ull* v, const float* p) {
    const ulonglong2* q = (const ulonglong2*)p;
    ulonglong2 a = q[0], b = q[1], c = q[2], d = q[3];
    v[0]=a.x; v[1]=a.y; v[2]=b.x; v[3]=b.y; v[4]=c.x; v[5]=c.y; v[6]=d.x; v[7]=d.y;
}

// One LSTM cell eval for ONE batch element, whole warp cooperating.
// Lane j holds gate rows {j, j+32} in registers (rows: i=0..15 f=16..31
// g=32..47 o=48..63 -> lane u<16: (i_u, g_u); lane u+16: (f_u, o_u)).
__device__ __forceinline__ void task1(
    const ull* __restrict__ wv, ull bi0, ull bi1,
    const float* __restrict__ inrow, const float* __restrict__ recrow,
    float& c, float* __restrict__ dst,
    float km, float am, float ab, bool lo, int lane)
{
    ull v0[8], v1[8];
    ld8u(v0, inrow);
    ld8u(v1, recrow);
    ull a0 = bi0, a1 = bi1;
#pragma unroll
    for (int kk = 0; kk < 8; ++kk) {
        a0 = fma2(wv[kk],      v0[kk], a0);
        a1 = fma2(wv[16 + kk], v0[kk], a1);
    }
#pragma unroll
    for (int kk = 0; kk < 8; ++kk) {
        a0 = fma2(wv[8 + kk],  v1[kk], a0);
        a1 = fma2(wv[24 + kk], v1[kk], a1);
    }
    float s0 = sum2(a0);
    float s1 = sum2(a1);
    float act0 = fmaf(0.5f, tanhap_(0.5f * s0), 0.5f);   // sigmoid
    float act1 = fmaf(am, tanhap_(km * s1), ab);         // tanh or sigmoid
    float p0 = __shfl_xor_sync(0xffffffffu, act0, 16);
    float p1 = __shfl_xor_sync(0xffffffffu, act1, 16);
    float fv = lo ? p0 : act0;
    float iv = lo ? act0 : p0;
    float gv = lo ? act1 : p1;
    float ov = lo ? p1 : act1;
    c = fmaf(fv, c, iv * gv);
    float h = ov * tanhap_(c);
    if (lo) dst[lane] = h;
}

// n tasks (n = 3 or 4, warp-uniform)
__device__ __forceinline__ void cellN(
    const ull* __restrict__ wv, ull bi0, ull bi1,
    const float* __restrict__ inb, const float* __restrict__ recb,
    float* __restrict__ c, float* __restrict__ dstb,
    float km, float am, float ab, bool lo, int lane, int n)
{
#pragma unroll
    for (int e = 0; e < 4; ++e)
        if (e < n)
            task1(wv, bi0, bi1, inb + 16 * e, recb + 16 * e,
                  c[e], dstb + 16 * e, km, am, ab, lo, lane);
}

// CTA: 512 threads = 16 warps; EPC=28 elems; grid 147 (one wave on 148 SMs).
// Warps 0-7: layer 0 ("A"); warps 8-15: layer 1 ("B"), one step behind.
// Task counts per warp {4,4,4,4,3,3,3,3}: warps (w, w+4) land on the same SMSP
// -> every SMSP carries exactly 7 A-tasks + 7 B-tasks per step (balanced).
__global__ void __launch_bounds__(512, 1) lstm_pair28(
    const float* __restrict__ x,
    const float* __restrict__ Wih0, const float* __restrict__ Whh0,
    const float* __restrict__ bih0, const float* __restrict__ bhh0,
    const float* __restrict__ Wih1, const float* __restrict__ Whh1,
    const float* __restrict__ bih1, const float* __restrict__ bhh1,
    const float* __restrict__ Wproj, const float* __restrict__ bproj,
    const float* __restrict__ gamma, const float* __restrict__ beta,
    float* __restrict__ out)
{
    __shared__ __align__(16) float h0b[2][EPC][16];
    __shared__ __align__(16) float h1b[2][EPC][16];
    __shared__ __align__(16) float4 xs4[2][8][16];   // [parity][A-warp][e*4+q]

    const int tid = threadIdx.x;
    const int w    = tid >> 5;
    const int lane = tid & 31;
    const bool isA = (w < 8);
    const bool lo  = (lane < 16);
    const int wp   = w & 7;
    const int nt    = (wp < 4) ? 4 : 3;                       // tasks for this warp
    const int ebase = (wp < 4) ? 4 * wp : 16 + 3 * (wp - 4);  // first elem
    const int elem0 = blockIdx.x * EPC;
    const int nelem = min(EPC, 4096 - elem0);
    const bool active = (ebase < nelem);       // whole pair active/inactive together
    const int bid = wp + 1;

    // ---- weights into registers: lane -> gate rows {lane, lane+32} ----
    ull wv[32];
    ull bi0, bi1;
    {
        const float* Wi = isA ? Wih0 : Wih1;
        const float* Wh = isA ? Whh0 : Whh1;
        const float* bi = isA ? bih0 : bih1;
        const float* bh = isA ? bhh0 : bhh1;
        int rA = lane, rB = lane + 32;
#pragma unroll
        for (int kk = 0; kk < 8; ++kk) {
            wv[kk]      = pk2(Wi[rA * 16 + 2 * kk], Wi[rA * 16 + 2 * kk + 1]);
            wv[8 + kk]  = pk2(Wh[rA * 16 + 2 * kk], Wh[rA * 16 + 2 * kk + 1]);
            wv[16 + kk] = pk2(Wi[rB * 16 + 2 * kk], Wi[rB * 16 + 2 * kk + 1]);
            wv[24 + kk] = pk2(Wh[rB * 16 + 2 * kk], Wh[rB * 16 + 2 * kk + 1]);
        }
        bi0 = pk2(bi[rA] + bh[rA], 0.f);
        bi1 = pk2(bi[rB] + bh[rB], 0.f);
    }
    const float km = lo ? 1.0f : 0.5f;
    const float am = lo ? 1.0f : 0.5f;
    const float ab = lo ? 0.0f : 0.5f;

    for (int idx = tid; idx < 2 * EPC * 16; idx += 512) {
        ((float*)h0b)[idx] = 0.f;
        ((float*)h1b)[idx] = 0.f;
    }

    // ---- warp-private x staging (A warps, lanes 0-15; e<nt only) ----
    const float4* xq = (const float4*)x;
    float4 xnA, xnB;
    const bool stager = isA && lo && ((lane >> 2) < nt) && active;
    if (stager) {
        int e = lane >> 2, q = lane & 3;
        xq = (const float4*)(x + ((size_t)(elem0 + ebase + e) * TT) * 16) + q;
        xs4[0][wp][lane] = xq[0];   // x[0]
        xnB = xq[4];                // x[1]
    }

    float c[4] = {0.f, 0.f, 0.f, 0.f};

    const float* inS1  = isA ? (const float*)&xs4[0][wp][0] : &h0b[1][ebase][0];
    const float* recS1 = isA ? &h0b[1][ebase][0] : &h1b[0][ebase][0];
    float*       dstS1 = isA ? &h0b[0][ebase][0] : &h1b[1][ebase][0];
    const float* inS2  = isA ? (const float*)&xs4[1][wp][0] : &h0b[0][ebase][0];
    const float* recS2 = isA ? &h0b[0][ebase][0] : &h1b[1][ebase][0];
    float*       dstS2 = isA ? &h0b[1][ebase][0] : &h1b[0][ebase][0];

    __syncthreads();

    if (active) {
#pragma unroll 1
        for (int t0 = 0; t0 < TT; t0 += 2) {
            // ===== S1: global step t0 =====
            if (isA) {
                if (stager) {
                    xs4[1][wp][lane] = xnB;
                    int tf = t0 + 2 < TT ? t0 + 2 : TT - 1;
                    xnA = xq[(size_t)tf * 4];
                }
                cellN(wv, bi0, bi1, inS1, recS1, c, dstS1, km, am, ab, lo, lane, nt);
            } else if (t0 > 0) {
                cellN(wv, bi0, bi1, inS1, recS1, c, dstS1, km, am, ab, lo, lane, nt);
            }
            PBAR(bid);
            // ===== S2: global step t0+1 =====
            if (stager) {
                xs4[0][wp][lane] = xnA;
                int tf = t0 + 3 < TT ? t0 + 3 : TT - 1;
                xnB = xq[(size_t)tf * 4];
            }
            cellN(wv, bi0, bi1, inS2, recS2, c, dstS2, km, am, ab, lo, lane, nt);
            PBAR(bid);
        }
        // ---- tail: B computes h1[TT-1] ----
        if (!isA)
            cellN(wv, bi0, bi1, inS1, recS1, c, dstS1, km, am, ab, lo, lane, nt);
    }
    __syncthreads();

    // ---- projection + LayerNorm + tanh (warp 0; lane = CTA-local elem) ----
    if (w == 0 && lane < nelem) {
        float hv[16];
#pragma unroll
        for (int k = 0; k < 16; ++k) hv[k] = h1b[1][lane][k];
        float z[16];
        float mu = 0.f;
#pragma unroll
        for (int j = 0; j < 16; ++j) {
            float s = bproj[j];
#pragma unroll
            for (int k = 0; k < 16; ++k) s = fmaf(Wproj[j * 16 + k], hv[k], s);
            z[j] = s;
            mu += s;
        }
        mu *= (1.0f / 16.0f);
        float var = 0.f;
#pragma unroll
        for (int j = 0; j < 16; ++j) { float d = z[j] - mu; var = fmaf(d, d, var); }
        var *= (1.0f / 16.0f);
        float rs = rsqrtf(var + 1e-5f);
#pragma unroll
        for (int j = 0; j < 16; ++j) {
            float zn = (z[j] - mu) * rs * gamma[j] + beta[j];
            out[(size_t)(elem0 + lane) * 16 + j] = tanh_(zn);
        }
    }
}

extern "C" void kernel_launch(void* const* d_in, const int* in_sizes, int n_in,
                              void* d_out, int out_size) {
    const float* x     = (const float*)d_in[0];
    const float* Wih0  = (const float*)d_in[1];
    const float* Whh0  = (const float*)d_in[2];
    const float* bih0  = (const float*)d_in[3];
    const float* bhh0  = (const float*)d_in[4];
    const float* Wih1  = (const float*)d_in[5];
    const float* Whh1  = (const float*)d_in[6];
    const float* bih1  = (const float*)d_in[7];
    const float* bhh1  = (const float*)d_in[8];
    const float* Wproj = (const float*)d_in[9];
    const float* bproj = (const float*)d_in[10];
    const float* gamma = (const float*)d_in[11];
    const float* beta  = (const float*)d_in[12];
    float* out = (float*)d_out;

    int B = in_sizes[0] / (TT * 16);       // 4096
    int grid = (B + EPC - 1) / EPC;        // 147 CTAs <= 148 SMs (one wave)

    lstm_pair28<<<grid, 512>>>(x, Wih0, Whh0, bih0, bhh0,
                               Wih1, Whh1, bih1, bhh1,
                               Wproj, bproj, gamma, beta, out);
}

// round 11
// speedup vs baseline: 1.0497x; 1.0497x over previous
#include <cuda_runtime.h>

#define TT 512
typedef unsigned long long ull;

// ---------- packed f32x2 helpers ----------
__device__ __forceinline__ ull pk2(float a, float b) {
    ull r; asm("mov.b64 %0, {%1,%2};" : "=l"(r) : "f"(a), "f"(b)); return r;
}
__device__ __forceinline__ float sum2(ull v) {
    float a, b; asm("mov.b64 {%0,%1}, %2;" : "=f"(a), "=f"(b) : "l"(v));
    return a + b;
}
__device__ __forceinline__ ull fma2(ull a, ull b, ull c) {
    ull d; asm("fma.rn.f32x2 %0, %1, %2, %3;" : "=l"(d) : "l"(a), "l"(b), "l"(c));
    return d;
}
__device__ __forceinline__ ull add2(ull a, ull b) {
    ull d; asm("add.rn.f32x2 %0, %1, %2;" : "=l"(d) : "l"(a), "l"(b));
    return d;
}

// ---------- activations ----------
__device__ __forceinline__ float tanhap_(float x) {     // MUFU tanh (recurrence)
    float r; asm("tanh.approx.f32 %0, %1;" : "=f"(r) : "f"(x)); return r;
}
__device__ __forceinline__ float rcpf_(float x) {
    float r; asm("rcp.approx.f32 %0, %1;" : "=f"(r) : "f"(x)); return r;
}
__device__ __forceinline__ float ex2f_(float x) {
    float r; asm("ex2.approx.f32 %0, %1;" : "=f"(r) : "f"(x)); return r;
}
__device__ __forceinline__ float tanh_(float x) {       // accurate (epilogue)
    float e = ex2f_(2.8853900817779268f * x);
    return 1.0f - 2.0f * rcpf_(e + 1.0f);
}

// pairwise named barrier: A-warp wp <-> B-warp wp, 64 threads
#define PBAR(id) asm volatile("bar.sync %0, %1;" :: "r"(id), "r"(64) : "memory")

// 4-elem cell eval, accumulator-major: 16 independent chains live, loads
// streamed as ulonglong2 chunks. Lane j holds gate rows {j, j+32} in regs
// (rows: i=0..15 f=16..31 g=32..47 o=48..63). Sigmoid rows (i/f/o) have
// 0.5 pre-folded into weights+bias, so sigmoid(x) = 0.5*tanh(s)+0.5 with
// s already halved; g rows unscaled (plain tanh).
__device__ __forceinline__ void cell4(
    const ull* __restrict__ wv, ull bi0, ull bi1,
    const float* __restrict__ inb, const float* __restrict__ recb,
    float* __restrict__ c, float* __restrict__ dstb,
    float am, float ab, bool lo, int lane)
{
    ull a0[4], a1[4], b0[4], b1[4];
#pragma unroll
    for (int e = 0; e < 4; ++e) { a0[e] = bi0; a1[e] = bi1; b0[e] = 0ULL; b1[e] = 0ULL; }
    // input half (weights wv[0..7] / wv[16..23])
#pragma unroll
    for (int j = 0; j < 4; ++j) {
#pragma unroll
        for (int e = 0; e < 4; ++e) {
            ulonglong2 q = ((const ulonglong2*)(inb + 16 * e))[j];
            a0[e] = fma2(wv[2 * j],      q.x, a0[e]);
            a1[e] = fma2(wv[16 + 2 * j], q.x, a1[e]);
            a0[e] = fma2(wv[2 * j + 1],      q.y, a0[e]);
            a1[e] = fma2(wv[16 + 2 * j + 1], q.y, a1[e]);
        }
    }
    // recurrent half (weights wv[8..15] / wv[24..31]) into independent chains
#pragma unroll
    for (int j = 0; j < 4; ++j) {
#pragma unroll
        for (int e = 0; e < 4; ++e) {
            ulonglong2 q = ((const ulonglong2*)(recb + 16 * e))[j];
            b0[e] = fma2(wv[8 + 2 * j],      q.x, b0[e]);
            b1[e] = fma2(wv[24 + 2 * j],     q.x, b1[e]);
            b0[e] = fma2(wv[8 + 2 * j + 1],      q.y, b0[e]);
            b1[e] = fma2(wv[24 + 2 * j + 1],     q.y, b1[e]);
        }
    }
#pragma unroll
    for (int e = 0; e < 4; ++e) {
        float s0 = sum2(add2(a0[e], b0[e]));
        float s1 = sum2(add2(a1[e], b1[e]));
        float act0 = fmaf(0.5f, tanhap_(s0), 0.5f);   // sigmoid (0.5 in weights)
        float act1 = fmaf(am, tanhap_(s1), ab);       // tanh (g) or sigmoid (o)
        float p0 = __shfl_xor_sync(0xffffffffu, act0, 16);
        float p1 = __shfl_xor_sync(0xffffffffu, act1, 16);
        float fv = lo ? p0 : act0;
        float iv = lo ? act0 : p0;
        float gv = lo ? act1 : p1;
        float ov = lo ? p1 : act1;
        c[e] = fmaf(fv, c[e], iv * gv);
        float h = ov * tanhap_(c[e]);
        if (lo) dstb[16 * e + lane] = h;
    }
}

// CTA: 512 threads = 16 warps; 32 elems; grid 128.
// Warps 0-7: layer 0 ("A"), elems 4w..4w+3. Warps 8-15: layer 1 ("B"),
// one step behind. Pairwise named barriers; warp-private x staging.
__global__ void __launch_bounds__(512, 1) lstm_pair3(
    const float* __restrict__ x,
    const float* __restrict__ Wih0, const float* __restrict__ Whh0,
    const float* __restrict__ bih0, const float* __restrict__ bhh0,
    const float* __restrict__ Wih1, const float* __restrict__ Whh1,
    const float* __restrict__ bih1, const float* __restrict__ bhh1,
    const float* __restrict__ Wproj, const float* __restrict__ bproj,
    const float* __restrict__ gamma, const float* __restrict__ beta,
    float* __restrict__ out)
{
    __shared__ __align__(16) float h0b[2][32][16];
    __shared__ __align__(16) float h1b[2][32][16];
    __shared__ __align__(16) float4 xs4[2][8][16];

    const int tid = threadIdx.x;
    const int w    = tid >> 5;
    const int lane = tid & 31;
    const bool isA = (w < 8);
    const bool lo  = (lane < 16);
    const int wp   = w & 7;
    const int ebase = wp * 4;
    const int elem0 = blockIdx.x * 32;
    const int bid = wp + 1;

    // ---- weights into registers, sigmoid rows pre-scaled by 0.5 ----
    // rA = lane (i/f rows: always sigmoid -> scale 0.5)
    // rB = lane+32 (g rows lanes<16: unscaled; o rows lanes>=16: 0.5)
    ull wv[32];
    ull bi0, bi1;
    {
        const float* Wi = isA ? Wih0 : Wih1;
        const float* Wh = isA ? Whh0 : Whh1;
        const float* bi = isA ? bih0 : bih1;
        const float* bh = isA ? bhh0 : bhh1;
        int rA = lane, rB = lane + 32;
        const float sA = 0.5f;
        const float sB = lo ? 1.0f : 0.5f;
#pragma unroll
        for (int kk = 0; kk < 8; ++kk) {
            wv[kk]      = pk2(sA * Wi[rA * 16 + 2 * kk], sA * Wi[rA * 16 + 2 * kk + 1]);
            wv[8 + kk]  = pk2(sA * Wh[rA * 16 + 2 * kk], sA * Wh[rA * 16 + 2 * kk + 1]);
            wv[16 + kk] = pk2(sB * Wi[rB * 16 + 2 * kk], sB * Wi[rB * 16 + 2 * kk + 1]);
            wv[24 + kk] = pk2(sB * Wh[rB * 16 + 2 * kk], sB * Wh[rB * 16 + 2 * kk + 1]);
        }
        bi0 = pk2(sA * (bi[rA] + bh[rA]), 0.f);
        bi1 = pk2(sB * (bi[rB] + bh[rB]), 0.f);
    }
    const float am = lo ? 1.0f : 0.5f;
    const float ab = lo ? 0.0f : 0.5f;

    for (int idx = tid; idx < 1024; idx += 512) {
        ((float*)h0b)[idx] = 0.f;
        ((float*)h1b)[idx] = 0.f;
    }

    // ---- warp-private x staging (A warps, lanes 0-15) ----
    const float4* xq = (const float4*)x;
    float4 xnA, xnB;
    if (isA) {
        int e = lane >> 2, q = lane & 3;
        xq = (const float4*)(x + ((size_t)(elem0 + ebase + e) * TT) * 16) + q;
        if (lo) {
            xs4[0][wp][lane] = xq[0];   // x[0]
            xnB = xq[4];                // x[1]
        }
    }

    float c[4] = {0.f, 0.f, 0.f, 0.f};

    const float* inS1  = isA ? (const float*)&xs4[0][wp][0] : &h0b[1][ebase][0];
    const float* recS1 = isA ? &h0b[1][ebase][0] : &h1b[0][ebase][0];
    float*       dstS1 = isA ? &h0b[0][ebase][0] : &h1b[1][ebase][0];
    const float* inS2  = isA ? (const float*)&xs4[1][wp][0] : &h0b[0][ebase][0];
    const float* recS2 = isA ? &h0b[0][ebase][0] : &h1b[1][ebase][0];
    float*       dstS2 = isA ? &h0b[1][ebase][0] : &h1b[0][ebase][0];

    __syncthreads();

#pragma unroll 1
    for (int t0 = 0; t0 < TT; t0 += 2) {
        // ===== S1: global step t0 =====
        if (isA) {
            if (lo) {
                xs4[1][wp][lane] = xnB;
                int tf = t0 + 2 < TT ? t0 + 2 : TT - 1;
                xnA = xq[(size_t)tf * 4];
            }
            cell4(wv, bi0, bi1, inS1, recS1, c, dstS1, am, ab, lo, lane);
        } else if (t0 > 0) {
            cell4(wv, bi0, bi1, inS1, recS1, c, dstS1, am, ab, lo, lane);
        }
        PBAR(bid);
        // ===== S2: global step t0+1 =====
        if (isA && lo) {
            xs4[0][wp][lane] = xnA;
            int tf = t0 + 3 < TT ? t0 + 3 : TT - 1;
            xnB = xq[(size_t)tf * 4];
        }
        cell4(wv, bi0, bi1, inS2, recS2, c, dstS2, am, ab, lo, lane);
        PBAR(bid);
    }

    // ---- tail: B computes h1[TT-1] ----
    if (!isA)
        cell4(wv, bi0, bi1, inS1, recS1, c, dstS1, am, ab, lo, lane);
    __syncthreads();

    // ---- projection + LayerNorm + tanh (warp 0; accurate tanh) ----
    if (w == 0) {
        float hv[16];
#pragma unroll
        for (int k = 0; k < 16; ++k) hv[k] = h1b[1][lane][k];
        float z[16];
        float mu = 0.f;
#pragma unroll
        for (int j = 0; j < 16; ++j) {
            float s = bproj[j];
#pragma unroll
            for (int k = 0; k < 16; ++k) s = fmaf(Wproj[j * 16 + k], hv[k], s);
            z[j] = s;
            mu += s;
        }
        mu *= (1.0f / 16.0f);
        float var = 0.f;
#pragma unroll
        for (int j = 0; j < 16; ++j) { float d = z[j] - mu; var = fmaf(d, d, var); }
        var *= (1.0f / 16.0f);
        float rs = rsqrtf(var + 1e-5f);
#pragma unroll
        for (int j = 0; j < 16; ++j) {
            float zn = (z[j] - mu) * rs * gamma[j] + beta[j];
            out[(size_t)(elem0 + lane) * 16 + j] = tanh_(zn);
        }
    }
}

extern "C" void kernel_launch(void* const* d_in, const int* in_sizes, int n_in,
                              void* d_out, int out_size) {
    const float* x     = (const float*)d_in[0];
    const float* Wih0  = (const float*)d_in[1];
    const float* Whh0  = (const float*)d_in[2];
    const float* bih0  = (const float*)d_in[3];
    const float* bhh0  = (const float*)d_in[4];
    const float* Wih1  = (const float*)d_in[5];
    const float* Whh1  = (const float*)d_in[6];
    const float* bih1  = (const float*)d_in[7];
    const float* bhh1  = (const float*)d_in[8];
    const float* Wproj = (const float*)d_in[9];
    const float* bproj = (const float*)d_in[10];
    const float* gamma = (const float*)d_in[11];
    const float* beta  = (const float*)d_in[12];
    float* out = (float*)d_out;

    int B = in_sizes[0] / (TT * 16);   // 4096
    int grid = B / 32;                 // 128 CTAs

    lstm_pair3<<<grid, 512>>>(x, Wih0, Whh0, bih0, bhh0,
                              Wih1, Whh1, bih1, bhh1,
                              Wproj, bproj, gamma, beta, out);
}

// round 12
// speedup vs baseline: 1.0570x; 1.0070x over previous
#include <cuda_runtime.h>

#define TT 512
typedef unsigned long long ull;

// ---------- packed f32x2 helpers ----------
__device__ __forceinline__ ull pk2(float a, float b) {
    ull r; asm("mov.b64 %0, {%1,%2};" : "=l"(r) : "f"(a), "f"(b)); return r;
}
__device__ __forceinline__ float sum2(ull v) {
    float a, b; asm("mov.b64 {%0,%1}, %2;" : "=f"(a), "=f"(b) : "l"(v));
    return a + b;
}
__device__ __forceinline__ ull fma2(ull a, ull b, ull c) {
    ull d; asm("fma.rn.f32x2 %0, %1, %2, %3;" : "=l"(d) : "l"(a), "l"(b), "l"(c));
    return d;
}
__device__ __forceinline__ ull add2(ull a, ull b) {
    ull d; asm("add.rn.f32x2 %0, %1, %2;" : "=l"(d) : "l"(a), "l"(b));
    return d;
}

// ---------- activations ----------
__device__ __forceinline__ float tanhap_(float x) {     // MUFU tanh (recurrence)
    float r; asm("tanh.approx.f32 %0, %1;" : "=f"(r) : "f"(x)); return r;
}
__device__ __forceinline__ float rcpf_(float x) {
    float r; asm("rcp.approx.f32 %0, %1;" : "=f"(r) : "f"(x)); return r;
}
__device__ __forceinline__ float ex2f_(float x) {
    float r; asm("ex2.approx.f32 %0, %1;" : "=f"(r) : "f"(x)); return r;
}
__device__ __forceinline__ float tanh_(float x) {       // accurate (epilogue)
    float e = ex2f_(2.8853900817779268f * x);
    return 1.0f - 2.0f * rcpf_(e + 1.0f);
}

// pairwise named barrier: A-warp wp <-> B-warp wp, 64 threads
#define PBAR(id) asm volatile("bar.sync %0, %1;" :: "r"(id), "r"(64) : "memory")

// 4-elem cell eval, accumulator-major (R11). Lane j holds gate rows
// {j, j+32} in regs. Sigmoid rows pre-scaled by 0.5 in weights+bias.
// No __restrict__ on in/rec/dst: callers may alias across steps; all loads
// of a task precede its store and __syncwarp orders cross-step reuse.
__device__ __forceinline__ void cell4(
    const ull* __restrict__ wv, ull bi0, ull bi1,
    const float* inb, const float* recb,
    float* __restrict__ c, float* dstb,
    float am, float ab, bool lo, int lane)
{
    ull a0[4], a1[4], b0[4], b1[4];
#pragma unroll
    for (int e = 0; e < 4; ++e) { a0[e] = bi0; a1[e] = bi1; b0[e] = 0ULL; b1[e] = 0ULL; }
#pragma unroll
    for (int j = 0; j < 4; ++j) {
#pragma unroll
        for (int e = 0; e < 4; ++e) {
            ulonglong2 q = ((const ulonglong2*)(inb + 16 * e))[j];
            a0[e] = fma2(wv[2 * j],          q.x, a0[e]);
            a1[e] = fma2(wv[16 + 2 * j],     q.x, a1[e]);
            a0[e] = fma2(wv[2 * j + 1],      q.y, a0[e]);
            a1[e] = fma2(wv[16 + 2 * j + 1], q.y, a1[e]);
        }
    }
#pragma unroll
    for (int j = 0; j < 4; ++j) {
#pragma unroll
        for (int e = 0; e < 4; ++e) {
            ulonglong2 q = ((const ulonglong2*)(recb + 16 * e))[j];
            b0[e] = fma2(wv[8 + 2 * j],      q.x, b0[e]);
            b1[e] = fma2(wv[24 + 2 * j],     q.x, b1[e]);
            b0[e] = fma2(wv[8 + 2 * j + 1],  q.y, b0[e]);
            b1[e] = fma2(wv[24 + 2 * j + 1], q.y, b1[e]);
        }
    }
#pragma unroll
    for (int e = 0; e < 4; ++e) {
        float s0 = sum2(add2(a0[e], b0[e]));
        float s1 = sum2(add2(a1[e], b1[e]));
        float act0 = fmaf(0.5f, tanhap_(s0), 0.5f);
        float act1 = fmaf(am, tanhap_(s1), ab);
        float p0 = __shfl_xor_sync(0xffffffffu, act0, 16);
        float p1 = __shfl_xor_sync(0xffffffffu, act1, 16);
        float fv = lo ? p0 : act0;
        float iv = lo ? act0 : p0;
        float gv = lo ? act1 : p1;
        float ov = lo ? p1 : act1;
        c[e] = fmaf(fv, c[e], iv * gv);
        float h = ov * tanhap_(c[e]);
        if (lo) dstb[16 * e + lane] = h;
    }
}

// CTA: 512 threads = 16 warps; 32 elems; grid 128.
// 2 global steps per barrier interval. h0 ring is 4-deep (slot = t & 3):
//   interval P (t0%4==0): A writes slots 0,1; B reads slots 2,3 (steps t0-2,t0-1)
//   interval Q (t0%4==2): A writes slots 2,3; B reads slots 0,1 (steps t0,t0+1... lagged)
// h1 is B-warp-local, double-buffered (even step: rec buf0 -> dst buf1).
__global__ void __launch_bounds__(512, 1) lstm_pair4(
    const float* __restrict__ x,
    const float* __restrict__ Wih0, const float* __restrict__ Whh0,
    const float* __restrict__ bih0, const float* __restrict__ bhh0,
    const float* __restrict__ Wih1, const float* __restrict__ Whh1,
    const float* __restrict__ bih1, const float* __restrict__ bhh1,
    const float* __restrict__ Wproj, const float* __restrict__ bproj,
    const float* __restrict__ gamma, const float* __restrict__ beta,
    float* __restrict__ out)
{
    __shared__ __align__(16) float h0r[4][32][16];   // ring, 8 KB
    __shared__ __align__(16) float h1b[2][32][16];   // B-local double buffer
    __shared__ __align__(16) float4 xs4[2][8][16];   // [step-in-interval][A-warp]

    const int tid = threadIdx.x;
    const int w    = tid >> 5;
    const int lane = tid & 31;
    const bool isA = (w < 8);
    const bool lo  = (lane < 16);
    const int wp   = w & 7;
    const int ebase = wp * 4;
    const int elem0 = blockIdx.x * 32;
    const int bid = wp + 1;

    // ---- weights into registers, sigmoid rows pre-scaled by 0.5 ----
    ull wv[32];
    ull bi0, bi1;
    {
        const float* Wi = isA ? Wih0 : Wih1;
        const float* Wh = isA ? Whh0 : Whh1;
        const float* bi = isA ? bih0 : bih1;
        const float* bh = isA ? bhh0 : bhh1;
        int rA = lane, rB = lane + 32;
        const float sA = 0.5f;
        const float sB = lo ? 1.0f : 0.5f;
#pragma unroll
        for (int kk = 0; kk < 8; ++kk) {
            wv[kk]      = pk2(sA * Wi[rA * 16 + 2 * kk], sA * Wi[rA * 16 + 2 * kk + 1]);
            wv[8 + kk]  = pk2(sA * Wh[rA * 16 + 2 * kk], sA * Wh[rA * 16 + 2 * kk + 1]);
            wv[16 + kk] = pk2(sB * Wi[rB * 16 + 2 * kk], sB * Wi[rB * 16 + 2 * kk + 1]);
            wv[24 + kk] = pk2(sB * Wh[rB * 16 + 2 * kk], sB * Wh[rB * 16 + 2 * kk + 1]);
        }
        bi0 = pk2(sA * (bi[rA] + bh[rA]), 0.f);
        bi1 = pk2(sB * (bi[rB] + bh[rB]), 0.f);
    }
    const float am = lo ? 1.0f : 0.5f;
    const float ab = lo ? 0.0f : 0.5f;

    for (int idx = tid; idx < 4 * 32 * 16; idx += 512) ((float*)h0r)[idx] = 0.f;
    for (int idx = tid; idx < 2 * 32 * 16; idx += 512) ((float*)h1b)[idx] = 0.f;

    // ---- warp-private x staging (A warps, lanes 0-15) ----
    const float4* xq = (const float4*)x;
    float4 xn0, xn1;
    if (isA && lo) {
        int e = lane >> 2, q = lane & 3;
        xq = (const float4*)(x + ((size_t)(elem0 + ebase + e) * TT) * 16) + q;
        xn0 = xq[0];        // x[0]
        xn1 = xq[4];        // x[1]
    }

    float c[4] = {0.f, 0.f, 0.f, 0.f};

    const float* xr0 = (const float*)&xs4[0][wp][0];
    const float* xr1 = (const float*)&xs4[1][wp][0];
    float* h0s0 = &h0r[0][ebase][0];
    float* h0s1 = &h0r[1][ebase][0];
    float* h0s2 = &h0r[2][ebase][0];
    float* h0s3 = &h0r[3][ebase][0];
    float* h1b0 = &h1b[0][ebase][0];
    float* h1b1 = &h1b[1][ebase][0];

    __syncthreads();

#pragma unroll 1
    for (int t0 = 0; t0 < TT; t0 += 4) {
        // ===== interval P: A steps t0,t0+1 (slots 0,1); B steps t0-2,t0-1 (slots 2,3) =====
        if (isA) {
            if (lo) {
                xs4[0][wp][lane] = xn0;
                xs4[1][wp][lane] = xn1;
                xn0 = xq[(size_t)(t0 + 2) * 4];            // x[t0+2] (t0+2 <= 510)
                xn1 = xq[(size_t)(t0 + 3) * 4];            // x[t0+3] (<= 511)
            }
            __syncwarp();
            cell4(wv, bi0, bi1, xr0, h0s3, c, h0s0, am, ab, lo, lane);
            __syncwarp();
            cell4(wv, bi0, bi1, xr1, h0s0, c, h0s1, am, ab, lo, lane);
        } else if (t0 > 0) {
            cell4(wv, bi0, bi1, h0s2, h1b0, c, h1b1, am, ab, lo, lane);
            __syncwarp();
            cell4(wv, bi0, bi1, h0s3, h1b1, c, h1b0, am, ab, lo, lane);
        }
        PBAR(bid);
        // ===== interval Q: A steps t0+2,t0+3 (slots 2,3); B steps t0,t0+1 (slots 0,1) =====
        if (isA) {
            if (lo) {
                xs4[0][wp][lane] = xn0;
                xs4[1][wp][lane] = xn1;
                int tf0 = t0 + 4 < TT ? t0 + 4 : TT - 1;   // clamp at the end
                int tf1 = t0 + 5 < TT ? t0 + 5 : TT - 1;
                xn0 = xq[(size_t)tf0 * 4];
                xn1 = xq[(size_t)tf1 * 4];
            }
            __syncwarp();
            cell4(wv, bi0, bi1, xr0, h0s1, c, h0s2, am, ab, lo, lane);
            __syncwarp();
            cell4(wv, bi0, bi1, xr1, h0s2, c, h0s3, am, ab, lo, lane);
        } else {
            cell4(wv, bi0, bi1, h0s0, h1b0, c, h1b1, am, ab, lo, lane);
            __syncwarp();
            cell4(wv, bi0, bi1, h0s1, h1b1, c, h1b0, am, ab, lo, lane);
        }
        PBAR(bid);
    }

    // ---- tail: B steps 510 (slot 2), 511 (slot 3) ----
    if (!isA) {
        cell4(wv, bi0, bi1, h0s2, h1b0, c, h1b1, am, ab, lo, lane);
        __syncwarp();
        cell4(wv, bi0, bi1, h0s3, h1b1, c, h1b0, am, ab, lo, lane);
    }
    __syncthreads();

    // ---- projection + LayerNorm + tanh (warp 0; final h1 in h1b[0]) ----
    if (w == 0) {
        float hv[16];
#pragma unroll
        for (int k = 0; k < 16; ++k) hv[k] = h1b[0][lane][k];
        float z[16];
        float mu = 0.f;
#pragma unroll
        for (int j = 0; j < 16; ++j) {
            float s = bproj[j];
#pragma unroll
            for (int k = 0; k < 16; ++k) s = fmaf(Wproj[j * 16 + k], hv[k], s);
            z[j] = s;
            mu += s;
        }
        mu *= (1.0f / 16.0f);
        float var = 0.f;
#pragma unroll
        for (int j = 0; j < 16; ++j) { float d = z[j] - mu; var = fmaf(d, d, var); }
        var *= (1.0f / 16.0f);
        float rs = rsqrtf(var + 1e-5f);
#pragma unroll
        for (int j = 0; j < 16; ++j) {
            float zn = (z[j] - mu) * rs * gamma[j] + beta[j];
            out[(size_t)(elem0 + lane) * 16 + j] = tanh_(zn);
        }
    }
}

extern "C" void kernel_launch(void* const* d_in, const int* in_sizes, int n_in,
                              void* d_out, int out_size) {
    const float* x     = (const float*)d_in[0];
    const float* Wih0  = (const float*)d_in[1];
    const float* Whh0  = (const float*)d_in[2];
    const float* bih0  = (const float*)d_in[3];
    const float* bhh0  = (const float*)d_in[4];
    const float* Wih1  = (const float*)d_in[5];
    const float* Whh1  = (const float*)d_in[6];
    const float* bih1  = (const float*)d_in[7];
    const float* bhh1  = (const float*)d_in[8];
    const float* Wproj = (const float*)d_in[9];
    const float* bproj = (const float*)d_in[10];
    const float* gamma = (const float*)d_in[11];
    const float* beta  = (const float*)d_in[12];
    float* out = (float*)d_out;

    int B = in_sizes[0] / (TT * 16);   // 4096
    int grid = B / 32;                 // 128 CTAs

    lstm_pair4<<<grid, 512>>>(x, Wih0, Whh0, bih0, bhh0,
                              Wih1, Whh1, bih1, bhh1,
                              Wproj, bproj, gamma, beta, out);
}

// round 13
// speedup vs baseline: 1.1218x; 1.0613x over previous
#include <cuda_runtime.h>

#define TT 512
typedef unsigned long long ull;

// ---------- packed f32x2 helpers ----------
__device__ __forceinline__ ull pk2(float a, float b) {
    ull r; asm("mov.b64 %0, {%1,%2};" : "=l"(r) : "f"(a), "f"(b)); return r;
}
__device__ __forceinline__ float sum2(ull v) {
    float a, b; asm("mov.b64 {%0,%1}, %2;" : "=f"(a), "=f"(b) : "l"(v));
    return a + b;
}
__device__ __forceinline__ ull fma2(ull a, ull b, ull c) {
    ull d; asm("fma.rn.f32x2 %0, %1, %2, %3;" : "=l"(d) : "l"(a), "l"(b), "l"(c));
    return d;
}
__device__ __forceinline__ ull mul2(ull a, ull b) {
    ull d; asm("mul.rn.f32x2 %0, %1, %2;" : "=l"(d) : "l"(a), "l"(b));
    return d;
}
__device__ __forceinline__ ull add2(ull a, ull b) {
    ull d; asm("add.rn.f32x2 %0, %1, %2;" : "=l"(d) : "l"(a), "l"(b));
    return d;
}

// ---------- activations ----------
__device__ __forceinline__ float tanhap_(float x) {     // MUFU tanh (recurrence)
    float r; asm("tanh.approx.f32 %0, %1;" : "=f"(r) : "f"(x)); return r;
}
__device__ __forceinline__ float rcpf_(float x) {
    float r; asm("rcp.approx.f32 %0, %1;" : "=f"(r) : "f"(x)); return r;
}
__device__ __forceinline__ float ex2f_(float x) {
    float r; asm("ex2.approx.f32 %0, %1;" : "=f"(r) : "f"(x)); return r;
}
__device__ __forceinline__ float tanh_(float x) {       // accurate (epilogue)
    float e = ex2f_(2.8853900817779268f * x);
    return 1.0f - 2.0f * rcpf_(e + 1.0f);
}

// pairwise named barrier: A-warp wp <-> B-warp wp, 64 threads
#define PBAR(id) asm volatile("bar.sync %0, %1;" :: "r"(id), "r"(64) : "memory")

// 4-elem cell eval, accumulator-major, init-folded, asymmetric-role tail.
// Lane j holds gate rows {j, j+32} in regs. Sigmoid rows pre-scaled by 0.5.
// Tail roles: lo lanes (rows i,g) compute ig = i*g and ship it via ONE shfl;
// hi lanes (rows f,o) own the cell state c and store h. c in lo lanes is
// garbage and unused; h store comes from hi lanes only.
__device__ __forceinline__ void cell4(
    const ull* __restrict__ wv, ull bi0, ull bi1,
    const float* inb, const float* recb,
    float* __restrict__ c, float* dstb,
    float am, float ab, bool lo, int lane)
{
    ull a0[4], a1[4], b0[4], b1[4];
    // input half (wv[0..7] / wv[16..23]); j=0 folds bias into the first fma
#pragma unroll
    for (int e = 0; e < 4; ++e) {
        ulonglong2 q = ((const ulonglong2*)(inb + 16 * e))[0];
        a0[e] = fma2(wv[0],  q.x, bi0);
        a1[e] = fma2(wv[16], q.x, bi1);
        a0[e] = fma2(wv[1],  q.y, a0[e]);
        a1[e] = fma2(wv[17], q.y, a1[e]);
    }
#pragma unroll
    for (int j = 1; j < 4; ++j) {
#pragma unroll
        for (int e = 0; e < 4; ++e) {
            ulonglong2 q = ((const ulonglong2*)(inb + 16 * e))[j];
            a0[e] = fma2(wv[2 * j],          q.x, a0[e]);
            a1[e] = fma2(wv[16 + 2 * j],     q.x, a1[e]);
            a0[e] = fma2(wv[2 * j + 1],      q.y, a0[e]);
            a1[e] = fma2(wv[16 + 2 * j + 1], q.y, a1[e]);
        }
    }
    // recurrent half (wv[8..15] / wv[24..31]); j=0 initializes via mul
#pragma unroll
    for (int e = 0; e < 4; ++e) {
        ulonglong2 q = ((const ulonglong2*)(recb + 16 * e))[0];
        b0[e] = mul2(wv[8],  q.x);
        b1[e] = mul2(wv[24], q.x);
        b0[e] = fma2(wv[9],  q.y, b0[e]);
        b1[e] = fma2(wv[25], q.y, b1[e]);
    }
#pragma unroll
    for (int j = 1; j < 4; ++j) {
#pragma unroll
        for (int e = 0; e < 4; ++e) {
            ulonglong2 q = ((const ulonglong2*)(recb + 16 * e))[j];
            b0[e] = fma2(wv[8 + 2 * j],      q.x, b0[e]);
            b1[e] = fma2(wv[24 + 2 * j],     q.x, b1[e]);
            b0[e] = fma2(wv[8 + 2 * j + 1],  q.y, b0[e]);
            b1[e] = fma2(wv[24 + 2 * j + 1], q.y, b1[e]);
        }
    }
#pragma unroll
    for (int e = 0; e < 4; ++e) {
        float s0 = sum2(add2(a0[e], b0[e]));
        float s1 = sum2(add2(a1[e], b1[e]));
        float act0 = fmaf(0.5f, tanhap_(s0), 0.5f);   // i (lo) / f (hi)
        float act1 = fmaf(am, tanhap_(s1), ab);       // g (lo) / o (hi)
        float ig  = act0 * act1;                      // meaningful in lo lanes
        float igx = __shfl_xor_sync(0xffffffffu, ig, 16);  // hi <- lo's ig
        c[e] = fmaf(act0, c[e], igx);                 // hi: f*c + i*g
        float h = act1 * tanhap_(c[e]);               // hi: o * tanh(c)
        if (!lo) dstb[16 * e + lane - 16] = h;
    }
}

// CTA: 512 threads = 16 warps; 32 elems; grid 128.
// 2 global steps per barrier interval (R12 schedule). h0 ring 4-deep;
// h1 B-local double buffer; warp-private x staging.
__global__ void __launch_bounds__(512, 1) lstm_pair5(
    const float* __restrict__ x,
    const float* __restrict__ Wih0, const float* __restrict__ Whh0,
    const float* __restrict__ bih0, const float* __restrict__ bhh0,
    const float* __restrict__ Wih1, const float* __restrict__ Whh1,
    const float* __restrict__ bih1, const float* __restrict__ bhh1,
    const float* __restrict__ Wproj, const float* __restrict__ bproj,
    const float* __restrict__ gamma, const float* __restrict__ beta,
    float* __restrict__ out)
{
    __shared__ __align__(16) float h0r[4][32][16];   // ring, 8 KB
    __shared__ __align__(16) float h1b[2][32][16];   // B-local double buffer
    __shared__ __align__(16) float4 xs4[2][8][16];   // [step-in-interval][A-warp]

    const int tid = threadIdx.x;
    const int w    = tid >> 5;
    const int lane = tid & 31;
    const bool isA = (w < 8);
    const bool lo  = (lane < 16);
    const int wp   = w & 7;
    const int ebase = wp * 4;
    const int elem0 = blockIdx.x * 32;
    const int bid = wp + 1;

    // ---- weights into registers, sigmoid rows pre-scaled by 0.5 ----
    ull wv[32];
    ull bi0, bi1;
    {
        const float* Wi = isA ? Wih0 : Wih1;
        const float* Wh = isA ? Whh0 : Whh1;
        const float* bi = isA ? bih0 : bih1;
        const float* bh = isA ? bhh0 : bhh1;
        int rA = lane, rB = lane + 32;
        const float sA = 0.5f;
        const float sB = lo ? 1.0f : 0.5f;
#pragma unroll
        for (int kk = 0; kk < 8; ++kk) {
            wv[kk]      = pk2(sA * Wi[rA * 16 + 2 * kk], sA * Wi[rA * 16 + 2 * kk + 1]);
            wv[8 + kk]  = pk2(sA * Wh[rA * 16 + 2 * kk], sA * Wh[rA * 16 + 2 * kk + 1]);
            wv[16 + kk] = pk2(sB * Wi[rB * 16 + 2 * kk], sB * Wi[rB * 16 + 2 * kk + 1]);
            wv[24 + kk] = pk2(sB * Wh[rB * 16 + 2 * kk], sB * Wh[rB * 16 + 2 * kk + 1]);
        }
        bi0 = pk2(sA * (bi[rA] + bh[rA]), 0.f);
        bi1 = pk2(sB * (bi[rB] + bh[rB]), 0.f);
    }
    const float am = lo ? 1.0f : 0.5f;
    const float ab = lo ? 0.0f : 0.5f;

    for (int idx = tid; idx < 4 * 32 * 16; idx += 512) ((float*)h0r)[idx] = 0.f;
    for (int idx = tid; idx < 2 * 32 * 16; idx += 512) ((float*)h1b)[idx] = 0.f;

    // ---- warp-private x staging (A warps, lanes 0-15) ----
    const float4* xq = (const float4*)x;
    float4 xn0, xn1;
    if (isA && lo) {
        int e = lane >> 2, q = lane & 3;
        xq = (const float4*)(x + ((size_t)(elem0 + ebase + e) * TT) * 16) + q;
        xn0 = xq[0];        // x[0]
        xn1 = xq[4];        // x[1]
    }

    float c[4] = {0.f, 0.f, 0.f, 0.f};

    const float* xr0 = (const float*)&xs4[0][wp][0];
    const float* xr1 = (const float*)&xs4[1][wp][0];
    float* h0s0 = &h0r[0][ebase][0];
    float* h0s1 = &h0r[1][ebase][0];
    float* h0s2 = &h0r[2][ebase][0];
    float* h0s3 = &h0r[3][ebase][0];
    float* h1b0 = &h1b[0][ebase][0];
    float* h1b1 = &h1b[1][ebase][0];

    __syncthreads();

#pragma unroll 1
    for (int t0 = 0; t0 < TT; t0 += 4) {
        // ===== interval P: A steps t0,t0+1 (slots 0,1); B steps t0-2,t0-1 =====
        if (isA) {
            if (lo) {
                xs4[0][wp][lane] = xn0;
                xs4[1][wp][lane] = xn1;
                xn0 = xq[(size_t)(t0 + 2) * 4];            // x[t0+2]
                xn1 = xq[(size_t)(t0 + 3) * 4];            // x[t0+3]
            }
            __syncwarp();
            cell4(wv, bi0, bi1, xr0, h0s3, c, h0s0, am, ab, lo, lane);
            __syncwarp();
            cell4(wv, bi0, bi1, xr1, h0s0, c, h0s1, am, ab, lo, lane);
        } else if (t0 > 0) {
            cell4(wv, bi0, bi1, h0s2, h1b0, c, h1b1, am, ab, lo, lane);
            __syncwarp();
            cell4(wv, bi0, bi1, h0s3, h1b1, c, h1b0, am, ab, lo, lane);
        }
        PBAR(bid);
        // ===== interval Q: A steps t0+2,t0+3 (slots 2,3); B steps t0,t0+1 =====
        if (isA) {
            if (lo) {
                xs4[0][wp][lane] = xn0;
                xs4[1][wp][lane] = xn1;
                int tf0 = t0 + 4 < TT ? t0 + 4 : TT - 1;
                int tf1 = t0 + 5 < TT ? t0 + 5 : TT - 1;
                xn0 = xq[(size_t)tf0 * 4];
                xn1 = xq[(size_t)tf1 * 4];
            }
            __syncwarp();
            cell4(wv, bi0, bi1, xr0, h0s1, c, h0s2, am, ab, lo, lane);
            __syncwarp();
            cell4(wv, bi0, bi1, xr1, h0s2, c, h0s3, am, ab, lo, lane);
        } else {
            cell4(wv, bi0, bi1, h0s0, h1b0, c, h1b1, am, ab, lo, lane);
            __syncwarp();
            cell4(wv, bi0, bi1, h0s1, h1b1, c, h1b0, am, ab, lo, lane);
        }
        PBAR(bid);
    }

    // ---- tail: B steps 510 (slot 2), 511 (slot 3) ----
    if (!isA) {
        cell4(wv, bi0, bi1, h0s2, h1b0, c, h1b1, am, ab, lo, lane);
        __syncwarp();
        cell4(wv, bi0, bi1, h0s3, h1b1, c, h1b0, am, ab, lo, lane);
    }
    __syncthreads();

    // ---- projection + LayerNorm + tanh (warp 0; final h1 in h1b[0]) ----
    if (w == 0) {
        float hv[16];
#pragma unroll
        for (int k = 0; k < 16; ++k) hv[k] = h1b[0][lane][k];
        float z[16];
        float mu = 0.f;
#pragma unroll
        for (int j = 0; j < 16; ++j) {
            float s = bproj[j];
#pragma unroll
            for (int k = 0; k < 16; ++k) s = fmaf(Wproj[j * 16 + k], hv[k], s);
            z[j] = s;
            mu += s;
        }
        mu *= (1.0f / 16.0f);
        float var = 0.f;
#pragma unroll
        for (int j = 0; j < 16; ++j) { float d = z[j] - mu; var = fmaf(d, d, var); }
        var *= (1.0f / 16.0f);
        float rs = rsqrtf(var + 1e-5f);
#pragma unroll
        for (int j = 0; j < 16; ++j) {
            float zn = (z[j] - mu) * rs * gamma[j] + beta[j];
            out[(size_t)(elem0 + lane) * 16 + j] = tanh_(zn);
        }
    }
}

extern "C" void kernel_launch(void* const* d_in, const int* in_sizes, int n_in,
                              void* d_out, int out_size) {
    const float* x     = (const float*)d_in[0];
    const float* Wih0  = (const float*)d_in[1];
    const float* Whh0  = (const float*)d_in[2];
    const float* bih0  = (const float*)d_in[3];
    const float* bhh0  = (const float*)d_in[4];
    const float* Wih1  = (const float*)d_in[5];
    const float* Whh1  = (const float*)d_in[6];
    const float* bih1  = (const float*)d_in[7];
    const float* bhh1  = (const float*)d_in[8];
    const float* Wproj = (const float*)d_in[9];
    const float* bproj = (const float*)d_in[10];
    const float* gamma = (const float*)d_in[11];
    const float* beta  = (const float*)d_in[12];
    float* out = (float*)d_out;

    int B = in_sizes[0] / (TT * 16);   // 4096
    int grid = B / 32;                 // 128 CTAs

    lstm_pair5<<<grid, 512>>>(x, Wih0, Whh0, bih0, bhh0,
                              Wih1, Whh1, bih1, bhh1,
                              Wproj, bproj, gamma, beta, out);
}

// round 14
// speedup vs baseline: 1.1574x; 1.0317x over previous
#include <cuda_runtime.h>

#define TT 512
typedef unsigned long long ull;

// ---------- packed f32x2 helpers ----------
__device__ __forceinline__ ull pk2(float a, float b) {
    ull r; asm("mov.b64 %0, {%1,%2};" : "=l"(r) : "f"(a), "f"(b)); return r;
}
__device__ __forceinline__ float sum2(ull v) {
    float a, b; asm("mov.b64 {%0,%1}, %2;" : "=f"(a), "=f"(b) : "l"(v));
    return a + b;
}
__device__ __forceinline__ ull fma2(ull a, ull b, ull c) {
    ull d; asm("fma.rn.f32x2 %0, %1, %2, %3;" : "=l"(d) : "l"(a), "l"(b), "l"(c));
    return d;
}
__device__ __forceinline__ ull mul2(ull a, ull b) {
    ull d; asm("mul.rn.f32x2 %0, %1, %2;" : "=l"(d) : "l"(a), "l"(b));
    return d;
}
__device__ __forceinline__ ull add2(ull a, ull b) {
    ull d; asm("add.rn.f32x2 %0, %1, %2;" : "=l"(d) : "l"(a), "l"(b));
    return d;
}

// ---------- activations ----------
__device__ __forceinline__ float tanhap_(float x) {     // MUFU tanh (recurrence)
    float r; asm("tanh.approx.f32 %0, %1;" : "=f"(r) : "f"(x)); return r;
}
__device__ __forceinline__ float rcpf_(float x) {
    float r; asm("rcp.approx.f32 %0, %1;" : "=f"(r) : "f"(x)); return r;
}
__device__ __forceinline__ float ex2f_(float x) {
    float r; asm("ex2.approx.f32 %0, %1;" : "=f"(r) : "f"(x)); return r;
}
__device__ __forceinline__ float tanh_(float x) {       // accurate (epilogue)
    float e = ex2f_(2.8853900817779268f * x);
    return 1.0f - 2.0f * rcpf_(e + 1.0f);
}

// pairwise named barrier: A-warp wp <-> B-warp wp, 64 threads
#define PBAR(id) asm volatile("bar.sync %0, %1;" :: "r"(id), "r"(64) : "memory")

// ---- x-phase: input-half accumulation for 4 tasks (bias folded) ----
// Independent of the recurrent state -> callable before the syncwarp that
// publishes h, letting ptxas overlap it with the previous step's tail.
__device__ __forceinline__ void xacc4(
    const ull* __restrict__ wv, ull bi0, ull bi1,
    const float* inb, ull* __restrict__ A0, ull* __restrict__ A1)
{
#pragma unroll
    for (int e = 0; e < 4; ++e) {
        ulonglong2 q = ((const ulonglong2*)(inb + 16 * e))[0];
        A0[e] = fma2(wv[0],  q.x, bi0);
        A1[e] = fma2(wv[16], q.x, bi1);
        A0[e] = fma2(wv[1],  q.y, A0[e]);
        A1[e] = fma2(wv[17], q.y, A1[e]);
    }
#pragma unroll
    for (int j = 1; j < 4; ++j) {
#pragma unroll
        for (int e = 0; e < 4; ++e) {
            ulonglong2 q = ((const ulonglong2*)(inb + 16 * e))[j];
            A0[e] = fma2(wv[2 * j],          q.x, A0[e]);
            A1[e] = fma2(wv[16 + 2 * j],     q.x, A1[e]);
            A0[e] = fma2(wv[2 * j + 1],      q.y, A0[e]);
            A1[e] = fma2(wv[16 + 2 * j + 1], q.y, A1[e]);
        }
    }
}

// ---- h-phase: recurrent half + asymmetric tail (R13) ----
// lo lanes (rows i,g) compute ig and ship via one shfl; hi lanes (f,o)
// own c and store h.
__device__ __forceinline__ void hfin4(
    const ull* __restrict__ wv,
    const float* recb, ull* __restrict__ A0, ull* __restrict__ A1,
    float* __restrict__ c, float* dstb,
    float am, float ab, bool lo, int lane)
{
    ull b0[4], b1[4];
#pragma unroll
    for (int e = 0; e < 4; ++e) {
        ulonglong2 q = ((const ulonglong2*)(recb + 16 * e))[0];
        b0[e] = mul2(wv[8],  q.x);
        b1[e] = mul2(wv[24], q.x);
        b0[e] = fma2(wv[9],  q.y, b0[e]);
        b1[e] = fma2(wv[25], q.y, b1[e]);
    }
#pragma unroll
    for (int j = 1; j < 4; ++j) {
#pragma unroll
        for (int e = 0; e < 4; ++e) {
            ulonglong2 q = ((const ulonglong2*)(recb + 16 * e))[j];
            b0[e] = fma2(wv[8 + 2 * j],      q.x, b0[e]);
            b1[e] = fma2(wv[24 + 2 * j],     q.x, b1[e]);
            b0[e] = fma2(wv[8 + 2 * j + 1],  q.y, b0[e]);
            b1[e] = fma2(wv[24 + 2 * j + 1], q.y, b1[e]);
        }
    }
#pragma unroll
    for (int e = 0; e < 4; ++e) {
        float s0 = sum2(add2(A0[e], b0[e]));
        float s1 = sum2(add2(A1[e], b1[e]));
        float act0 = fmaf(0.5f, tanhap_(s0), 0.5f);   // i (lo) / f (hi)
        float act1 = fmaf(am, tanhap_(s1), ab);       // g (lo) / o (hi)
        float ig  = act0 * act1;                      // meaningful in lo lanes
        float igx = __shfl_xor_sync(0xffffffffu, ig, 16);
        c[e] = fmaf(act0, c[e], igx);                 // hi: f*c + i*g
        float h = act1 * tanhap_(c[e]);               // hi: o * tanh(c)
        if (!lo) dstb[16 * e + lane - 16] = h;
    }
}

// CTA: 512 threads = 16 warps; 32 elems; grid 128.
// 2 steps per barrier interval; h0 ring 4-deep; h1 B-local double buffer.
// x staged one interval AHEAD (4 slots), so the PBAR covers STS->LDS ordering
// and the x-phase of step 2 hoists above the intra-interval syncwarp.
__global__ void __launch_bounds__(512, 1) lstm_pair6(
    const float* __restrict__ x,
    const float* __restrict__ Wih0, const float* __restrict__ Whh0,
    const float* __restrict__ bih0, const float* __restrict__ bhh0,
    const float* __restrict__ Wih1, const float* __restrict__ Whh1,
    const float* __restrict__ bih1, const float* __restrict__ bhh1,
    const float* __restrict__ Wproj, const float* __restrict__ bproj,
    const float* __restrict__ gamma, const float* __restrict__ beta,
    float* __restrict__ out)
{
    __shared__ __align__(16) float h0r[4][32][16];   // ring, 8 KB
    __shared__ __align__(16) float h1b[2][32][16];   // B-local double buffer
    __shared__ __align__(16) float4 xs4[4][8][16];   // [slot][A-warp][e*4+q]

    const int tid = threadIdx.x;
    const int w    = tid >> 5;
    const int lane = tid & 31;
    const bool isA = (w < 8);
    const bool lo  = (lane < 16);
    const int wp   = w & 7;
    const int ebase = wp * 4;
    const int elem0 = blockIdx.x * 32;
    const int bid = wp + 1;

    // ---- weights into registers, sigmoid rows pre-scaled by 0.5 ----
    ull wv[32];
    ull bi0, bi1;
    {
        const float* Wi = isA ? Wih0 : Wih1;
        const float* Wh = isA ? Whh0 : Whh1;
        const float* bi = isA ? bih0 : bih1;
        const float* bh = isA ? bhh0 : bhh1;
        int rA = lane, rB = lane + 32;
        const float sA = 0.5f;
        const float sB = lo ? 1.0f : 0.5f;
#pragma unroll
        for (int kk = 0; kk < 8; ++kk) {
            wv[kk]      = pk2(sA * Wi[rA * 16 + 2 * kk], sA * Wi[rA * 16 + 2 * kk + 1]);
            wv[8 + kk]  = pk2(sA * Wh[rA * 16 + 2 * kk], sA * Wh[rA * 16 + 2 * kk + 1]);
            wv[16 + kk] = pk2(sB * Wi[rB * 16 + 2 * kk], sB * Wi[rB * 16 + 2 * kk + 1]);
            wv[24 + kk] = pk2(sB * Wh[rB * 16 + 2 * kk], sB * Wh[rB * 16 + 2 * kk + 1]);
        }
        bi0 = pk2(sA * (bi[rA] + bh[rA]), 0.f);
        bi1 = pk2(sB * (bi[rB] + bh[rB]), 0.f);
    }
    const float am = lo ? 1.0f : 0.5f;
    const float ab = lo ? 0.0f : 0.5f;

    for (int idx = tid; idx < 4 * 32 * 16; idx += 512) ((float*)h0r)[idx] = 0.f;
    for (int idx = tid; idx < 2 * 32 * 16; idx += 512) ((float*)h1b)[idx] = 0.f;

    // ---- warp-private x staging (A warps, lanes 0-15) ----
    const float4* xq = (const float4*)x;
    float4 xn0, xn1;
    if (isA && lo) {
        int e = lane >> 2, q = lane & 3;
        xq = (const float4*)(x + ((size_t)(elem0 + ebase + e) * TT) * 16) + q;
        xs4[0][wp][lane] = xq[0];    // x[0]
        xs4[1][wp][lane] = xq[4];    // x[1]
        xn0 = xq[8];                 // x[2]
        xn1 = xq[12];                // x[3]
    }

    float c[4] = {0.f, 0.f, 0.f, 0.f};

    const float* xr0 = (const float*)&xs4[0][wp][0];
    const float* xr1 = (const float*)&xs4[1][wp][0];
    const float* xr2 = (const float*)&xs4[2][wp][0];
    const float* xr3 = (const float*)&xs4[3][wp][0];
    float* h0s0 = &h0r[0][ebase][0];
    float* h0s1 = &h0r[1][ebase][0];
    float* h0s2 = &h0r[2][ebase][0];
    float* h0s3 = &h0r[3][ebase][0];
    float* h1b0 = &h1b[0][ebase][0];
    float* h1b1 = &h1b[1][ebase][0];

    __syncthreads();

#pragma unroll 1
    for (int t0 = 0; t0 < TT; t0 += 4) {
        // ===== interval P: A steps t0,t0+1 (slots 0,1); B steps t0-2,t0-1 =====
        if (isA) {
            ull A0[4], A1[4];
            xacc4(wv, bi0, bi1, xr0, A0, A1);
            hfin4(wv, h0s3, A0, A1, c, h0s0, am, ab, lo, lane);
            ull B0[4], B1[4];
            xacc4(wv, bi0, bi1, xr1, B0, B1);        // hoisted x-phase (step t0+1)
            __syncwarp();
            hfin4(wv, h0s0, B0, B1, c, h0s1, am, ab, lo, lane);
            if (lo) {                                // stage next interval (Q)
                xs4[2][wp][lane] = xn0;              // x[t0+2]
                xs4[3][wp][lane] = xn1;              // x[t0+3]
                int tf0 = t0 + 4 < TT ? t0 + 4 : TT - 1;
                int tf1 = t0 + 5 < TT ? t0 + 5 : TT - 1;
                xn0 = xq[(size_t)tf0 * 4];
                xn1 = xq[(size_t)tf1 * 4];
            }
        } else if (t0 > 0) {
            ull A0[4], A1[4];
            xacc4(wv, bi0, bi1, h0s2, A0, A1);       // input h0[t0-2]
            hfin4(wv, h1b0, A0, A1, c, h1b1, am, ab, lo, lane);
            ull B0[4], B1[4];
            xacc4(wv, bi0, bi1, h0s3, B0, B1);       // hoisted (h0[t0-1] ready)
            __syncwarp();
            hfin4(wv, h1b1, B0, B1, c, h1b0, am, ab, lo, lane);
        }
        PBAR(bid);
        // ===== interval Q: A steps t0+2,t0+3 (slots 2,3); B steps t0,t0+1 =====
        if (isA) {
            ull A0[4], A1[4];
            xacc4(wv, bi0, bi1, xr2, A0, A1);
            hfin4(wv, h0s1, A0, A1, c, h0s2, am, ab, lo, lane);
            ull B0[4], B1[4];
            xacc4(wv, bi0, bi1, xr3, B0, B1);
            __syncwarp();
            hfin4(wv, h0s2, B0, B1, c, h0s3, am, ab, lo, lane);
            if (lo) {                                // stage next interval (P)
                xs4[0][wp][lane] = xn0;              // x[t0+4]
                xs4[1][wp][lane] = xn1;              // x[t0+5]
                int tf0 = t0 + 6 < TT ? t0 + 6 : TT - 1;
                int tf1 = t0 + 7 < TT ? t0 + 7 : TT - 1;
                xn0 = xq[(size_t)tf0 * 4];
                xn1 = xq[(size_t)tf1 * 4];
            }
        } else {
            ull A0[4], A1[4];
            xacc4(wv, bi0, bi1, h0s0, A0, A1);       // input h0[t0]
            hfin4(wv, h1b0, A0, A1, c, h1b1, am, ab, lo, lane);
            ull B0[4], B1[4];
            xacc4(wv, bi0, bi1, h0s1, B0, B1);
            __syncwarp();
            hfin4(wv, h1b1, B0, B1, c, h1b0, am, ab, lo, lane);
        }
        PBAR(bid);
    }

    // ---- tail: B steps 510 (slot 2), 511 (slot 3) ----
    if (!isA) {
        ull A0[4], A1[4];
        xacc4(wv, bi0, bi1, h0s2, A0, A1);
        hfin4(wv, h1b0, A0, A1, c, h1b1, am, ab, lo, lane);
        ull B0[4], B1[4];
        xacc4(wv, bi0, bi1, h0s3, B0, B1);
        __syncwarp();
        hfin4(wv, h1b1, B0, B1, c, h1b0, am, ab, lo, lane);
    }
    __syncthreads();

    // ---- projection + LayerNorm + tanh (warp 0; final h1 in h1b[0]) ----
    if (w == 0) {
        float hv[16];
#pragma unroll
        for (int k = 0; k < 16; ++k) hv[k] = h1b[0][lane][k];
        float z[16];
        float mu = 0.f;
#pragma unroll
        for (int j = 0; j < 16; ++j) {
            float s = bproj[j];
#pragma unroll
            for (int k = 0; k < 16; ++k) s = fmaf(Wproj[j * 16 + k], hv[k], s);
            z[j] = s;
            mu += s;
        }
        mu *= (1.0f / 16.0f);
        float var = 0.f;
#pragma unroll
        for (int j = 0; j < 16; ++j) { float d = z[j] - mu; var = fmaf(d, d, var); }
        var *= (1.0f / 16.0f);
        float rs = rsqrtf(var + 1e-5f);
#pragma unroll
        for (int j = 0; j < 16; ++j) {
            float zn = (z[j] - mu) * rs * gamma[j] + beta[j];
            out[(size_t)(elem0 + lane) * 16 + j] = tanh_(zn);
        }
    }
}

extern "C" void kernel_launch(void* const* d_in, const int* in_sizes, int n_in,
                              void* d_out, int out_size) {
    const float* x     = (const float*)d_in[0];
    const float* Wih0  = (const float*)d_in[1];
    const float* Whh0  = (const float*)d_in[2];
    const float* bih0  = (const float*)d_in[3];
    const float* bhh0  = (const float*)d_in[4];
    const float* Wih1  = (const float*)d_in[5];
    const float* Whh1  = (const float*)d_in[6];
    const float* bih1  = (const float*)d_in[7];
    const float* bhh1  = (const float*)d_in[8];
    const float* Wproj = (const float*)d_in[9];
    const float* bproj = (const float*)d_in[10];
    const float* gamma = (const float*)d_in[11];
    const float* beta  = (const float*)d_in[12];
    float* out = (float*)d_out;

    int B = in_sizes[0] / (TT * 16);   // 4096
    int grid = B / 32;                 // 128 CTAs

    lstm_pair6<<<grid, 512>>>(x, Wih0, Whh0, bih0, bhh0,
                              Wih1, Whh1, bih1, bhh1,
                              Wproj, bproj, gamma, beta, out);
}